// round 9
// baseline (speedup 1.0000x reference)
#include <cuda_runtime.h>

#define TT 128
#define BB 512
#define QQ 50
#define BQ (BB * QQ)                 // 25600
#define NUNITS ((TT - 1) * BB)       // 65024
#define GAMMA_F 0.99f
#define NCH 8
#define CHL 16
#define UNITS 10                     // units per k_pairs block (10*25 = 250 thr)
#define RST 52                       // smem row stride, 16B aligned

// Per-chunk affine composites per chain: rets[chunk_lo] = A*rets[chunk_hi+1] + B
__device__ float2 g_AB[NCH * BQ];
// Discounted returns, row gu = t*BB+b at [gu*QQ .. gu*QQ+49].
__device__ float g_ret[(TT - 1) * BQ];

// ---------------------------------------------------------------------------
// Kernel 1: chunk composites. ONE chain per thread (204,800 threads), chunk
// split into two independent 8-step halves for 2x MLP.
// ---------------------------------------------------------------------------
__global__ __launch_bounds__(256)
void k_scan(const float* __restrict__ reward,
            const int*   __restrict__ step_type,
            const float* __restrict__ discount,
            const float* __restrict__ tvalue,
            float*       __restrict__ out)
{
    const int n = blockIdx.x * 256 + threadIdx.x;   // 0..25599 chain
    const int c = blockIdx.y;
    if (c == 0 && n < BB) out[(TT - 1) * BB + n] = 0.0f;   // poisoned last row
    const int b = n / QQ;
    const int lo = c * CHL;
    const int hi = (c == NCH - 1) ? (TT - 2) : (lo + CHL - 1);

    float Au = 1.0f, Bu = 0.0f;
    float Al = 1.0f, Bl = 0.0f;
    #pragma unroll
    for (int k = 0; k < 8; ++k) {
        const int tu = hi - k;
        const int tl = lo + 7 - k;
        if (tu >= lo + 8) {
            float tv = tvalue[tu * BQ + n];
            int   il = step_type[tu * BB + b];
            float r  = reward[(tu + 1) * BB + b];
            float d  = discount[(tu + 1) * BB + b] * GAMMA_F;
            float a  = (il == 2) ? 0.0f : d;
            Au = a * Au;
            Bu = fmaf(a, Bu, (il == 2) ? tv : r);
        }
        {
            float tv = tvalue[tl * BQ + n];
            int   il = step_type[tl * BB + b];
            float r  = reward[(tl + 1) * BB + b];
            float d  = discount[(tl + 1) * BB + b] * GAMMA_F;
            float a  = (il == 2) ? 0.0f : d;
            Al = a * Al;
            Bl = fmaf(a, Bl, (il == 2) ? tv : r);
        }
    }
    g_AB[c * BQ + n] = make_float2(Al * Au, fmaf(Al, Bu, Bl));
}

// ---------------------------------------------------------------------------
// Kernel 2: fill returns. ONE chain per thread; compose tail composites
// (L2-hot) into the seed, then walk 16 steps in two 8-step prefetch groups.
// ---------------------------------------------------------------------------
__global__ __launch_bounds__(256)
void k_fill(const float* __restrict__ reward,
            const int*   __restrict__ step_type,
            const float* __restrict__ discount,
            const float* __restrict__ tvalue)
{
    const int n = blockIdx.x * 256 + threadIdx.x;   // 0..25599
    const int c = blockIdx.y;
    const int b = n / QQ;

    float carry = tvalue[(TT - 1) * BQ + n];        // rets[127]
    #pragma unroll
    for (int cc = NCH - 1; cc > 0; --cc) {
        if (cc > c) {
            float2 ab = g_AB[cc * BQ + n];
            carry = fmaf(ab.x, carry, ab.y);
        }
    }
    // carry == rets[hi+1]

    const int lo = c * CHL;
    const int hi = (c == NCH - 1) ? (TT - 2) : (lo + CHL - 1);

    #pragma unroll
    for (int g = 0; g < 2; ++g) {
        const int top = hi - g * 8;                 // walk t = top .. top-7
        float tv[8], a[8], bb[8];
        #pragma unroll
        for (int k = 0; k < 8; ++k) {
            const int t = top - k;
            if (t >= lo) {
                tv[k] = tvalue[t * BQ + n];
                int   il = step_type[t * BB + b];
                float r  = reward[(t + 1) * BB + b];
                float d  = discount[(t + 1) * BB + b] * GAMMA_F;
                a[k]  = (il == 2) ? 0.0f : d;
                bb[k] = (il == 2) ? tv[k] : r;
            }
        }
        #pragma unroll
        for (int k = 0; k < 8; ++k) {
            const int t = top - k;
            if (t >= lo) {
                carry = fmaf(a[k], carry, bb[k]);
                g_ret[t * BQ + n] = carry;
            }
        }
    }
}

// ---------------------------------------------------------------------------
// Kernel 3: pairwise quantile-Huber, one (u, j-pair) item per thread,
// one pass, fully unrolled, 64-reg budget for deep ILP.
//   x = ret_i - v_j;  m = min(|x|,1);  c = (x&sign)|m;  t = x - 0.5c
//   h = c*t, sgn(x)*h = m*t ;  loss_j = 0.5*S + (tau_j-0.5)*D
// ---------------------------------------------------------------------------

#define PAIR2(r2_, nv2_, S2_, D2_) do {                                        \
    unsigned long long x2_, c2_, m2_, t2_;                                     \
    asm("add.rn.f32x2 %0, %1, %2;" : "=l"(x2_) : "l"(r2_), "l"(nv2_));         \
    float xl_, xh_;                                                            \
    asm("mov.b64 {%0, %1}, %2;" : "=f"(xl_), "=f"(xh_) : "l"(x2_));            \
    float ml_ = fminf(fabsf(xl_), 1.0f);                                       \
    float mh_ = fminf(fabsf(xh_), 1.0f);                                       \
    float cl_ = __int_as_float((__float_as_int(xl_) & 0x80000000) |            \
                               __float_as_int(ml_));                           \
    float ch_ = __int_as_float((__float_as_int(xh_) & 0x80000000) |            \
                               __float_as_int(mh_));                           \
    asm("mov.b64 %0, {%1, %2};" : "=l"(c2_) : "f"(cl_), "f"(ch_));             \
    asm("mov.b64 %0, {%1, %2};" : "=l"(m2_) : "f"(ml_), "f"(mh_));             \
    asm("fma.rn.f32x2 %0, %1, %2, %3;" : "=l"(t2_)                             \
        : "l"(c2_), "l"(MH2), "l"(x2_));                                       \
    asm("fma.rn.f32x2 %0, %1, %2, %0;" : "+l"(S2_) : "l"(c2_), "l"(t2_));      \
    asm("fma.rn.f32x2 %0, %1, %2, %0;" : "+l"(D2_) : "l"(m2_), "l"(t2_));      \
} while (0)

__global__ __launch_bounds__(256, 4)
void k_pairs(const float* __restrict__ value,
             float*       __restrict__ out)
{
    __shared__ __align__(16) float s_ret[UNITS][RST];
    __shared__ float s_part[UNITS][QQ];

    const int tid = threadIdx.x;
    const int gu0 = blockIdx.x * UNITS;
    const int nu  = min(UNITS, NUNITS - gu0);

    const int u  = tid / 25;
    const int jp = tid - u * 25;

    // Stage: 250 float2 loads (rows gu0..gu0+nu-1 are gmem-contiguous).
    if (tid < UNITS * 25 && u < nu)
        ((float2*)&s_ret[u][0])[jp] =
            *(const float2*)&g_ret[gu0 * QQ + 2 * tid];
    __syncthreads();

    if (tid < UNITS * 25 && u < nu) {
        const int gu = gu0 + u;
        const float2 v2 = *(const float2*)&value[gu * QQ + 2 * jp];
        unsigned long long nv2a, nv2b;
        {
            float na = -v2.x, nb = -v2.y;
            asm("mov.b64 %0, {%1, %1};" : "=l"(nv2a) : "f"(na));
            asm("mov.b64 %0, {%1, %1};" : "=l"(nv2b) : "f"(nb));
        }
        const unsigned long long MH2 = 0xBF000000BF000000ULL;   // (-0.5,-0.5)
        unsigned long long S2a = 0, D2a = 0, S2b = 0, D2b = 0;

        const ulonglong2* rp2 = (const ulonglong2*)&s_ret[u][0];
        #pragma unroll
        for (int p = 0; p < 12; ++p) {               // 48 returns via LDS.128
            ulonglong2 rr = rp2[p];
            PAIR2(rr.x, nv2a, S2a, D2a);
            PAIR2(rr.x, nv2b, S2b, D2b);
            PAIR2(rr.y, nv2a, S2a, D2a);
            PAIR2(rr.y, nv2b, S2b, D2b);
        }
        {                                            // returns 48, 49
            unsigned long long rt_ = *(const unsigned long long*)&s_ret[u][48];
            PAIR2(rt_, nv2a, S2a, D2a);
            PAIR2(rt_, nv2b, S2b, D2b);
        }

        float sl, sh, dl, dh;
        asm("mov.b64 {%0, %1}, %2;" : "=f"(sl), "=f"(sh) : "l"(S2a));
        asm("mov.b64 {%0, %1}, %2;" : "=f"(dl), "=f"(dh) : "l"(D2a));
        const float taua = (2 * jp + 0.5f) * (1.0f / QQ);
        s_part[u][2 * jp]     = fmaf(taua - 0.5f, dl + dh, 0.5f * (sl + sh));

        asm("mov.b64 {%0, %1}, %2;" : "=f"(sl), "=f"(sh) : "l"(S2b));
        asm("mov.b64 {%0, %1}, %2;" : "=f"(dl), "=f"(dh) : "l"(D2b));
        const float taub = (2 * jp + 1.5f) * (1.0f / QQ);
        s_part[u][2 * jp + 1] = fmaf(taub - 0.5f, dl + dh, 0.5f * (sl + sh));
    }
    __syncthreads();

    // Deterministic fixed-order j-reduction, one thread per unit.
    if (tid < nu) {
        float s = 0.0f;
        #pragma unroll
        for (int j = 0; j < QQ; ++j) s += s_part[tid][j];
        out[gu0 + tid] = s * (1.0f / QQ);            // out idx t*BB+b == gu
    }
}

extern "C" void kernel_launch(void* const* d_in, const int* in_sizes, int n_in,
                              void* d_out, int out_size)
{
    const float* reward    = (const float*)d_in[0];
    const int*   step_type = (const int*)  d_in[1];
    const float* discount  = (const float*)d_in[2];
    const float* value     = (const float*)d_in[3];
    const float* tvalue    = (const float*)d_in[4];
    float*       out       = (float*)d_out;

    dim3 gs(BQ / 256, NCH);                          // (100, 8), 256-thr blocks
    k_scan<<<gs, 256>>>(reward, step_type, discount, tvalue, out);
    k_fill<<<gs, 256>>>(reward, step_type, discount, tvalue);

    const int nblocks = (NUNITS + UNITS - 1) / UNITS;   // 6503
    k_pairs<<<nblocks, 256>>>(value, out);
}